// round 10
// baseline (speedup 1.0000x reference)
#include <cuda_runtime.h>

#define LAYERS 12
#define NROW   4096
#define DD     16
#define TPB    256
#define QPT    4                                   // quarter-rows per thread
#define NBLK   192                                 // 16 blocks per layer
#define NWARP  (TPB / 32)
#define FULL   0xffffffffu

// Per-layer accumulators, padded to 36 floats (144B, 16B-aligned) so finalize
// reads each row with 9 x LDG.128.
// Slots: [0..15]=sum p, [16..31]=sum v, [32]=sum diag, [33]=sum log(s).
// Zeroed at module load; finalize re-zeroes after use (deterministic replays).
__device__ __align__(16) float g_acc[LAYERS][36];

// ---------------------------------------------------------------------------
// Kernel 1: per-layer sums. Lean body; REDG atomics; no fences (PDL's
// implicit completion trigger provides full memory visibility to finalize).
// ---------------------------------------------------------------------------
__global__ void __launch_bounds__(TPB) accum_kernel(const float* __restrict__ x) {
    const int tid   = threadIdx.x;
    const int lane  = tid & 31;
    const int wid   = tid >> 5;
    const int layer = blockIdx.x >> 4;              // 16 blocks/layer, uniform

    // 4 quarter-rows from 4 independent rows; 4 consecutive lanes cover one row.
    const int qbase = blockIdx.x * (TPB * QPT) + tid;
    float4 a[QPT];
#pragma unroll
    for (int k = 0; k < QPT; k++)
        a[k] = reinterpret_cast<const float4*>(x)[qbase + k * TPB];

    // No max-subtract: inputs are N(0,1); exp() cannot overflow fp32.
    float r[8];                 // [0..3] = sum_k p[d], [4..7] = sum_k v[d]
    float diag  = 0.f;          // lane-local sum p*log_q
    float lgsum = 0.f;          // sum log(s) — identical across the 4 row lanes
#pragma unroll
    for (int i = 0; i < 4; i++) r[i] = r[i + 4] = 0.f;

#pragma unroll
    for (int k = 0; k < QPT; k++) {
        float v[4] = { a[k].x, a[k].y, a[k].z, a[k].w };
        float e[4];
        float u = 0.f, t = 0.f;
#pragma unroll
        for (int i = 0; i < 4; i++) {
            e[i] = __expf(v[i]);
            u += e[i];
            t = fmaf(e[i], v[i], t);            // lane-local sum e*v
        }
        float s = u;                             // row sum across 4 lanes
        s += __shfl_xor_sync(FULL, s, 1);
        s += __shfl_xor_sync(FULL, s, 2);
        const float inv = 1.0f / s;
        const float lg  = __logf(s);

        diag  = fmaf(inv, t - lg * u, diag);     // sum_i p*(v - log s)
        lgsum += lg;                              // group-uniform, every lane

#pragma unroll
        for (int i = 0; i < 4; i++) {
            r[i]     = fmaf(e[i], inv, r[i]);
            r[i + 4] += v[i];
        }
    }

    // diag: complete within the 4-lane group first (full 4-row diag, uniform)
    diag += __shfl_xor_sync(FULL, diag, 1);
    diag += __shfl_xor_sync(FULL, diag, 2);

    // ---- recursive-halving warp reduce of r: masks {4,8,16} (7 SHFLs) ----
    float t4[4];
    {
        const bool up = (lane & 4) != 0;
#pragma unroll
        for (int i = 0; i < 4; i++) {
            float snd  = up ? r[i] : r[i + 4];
            float recv = __shfl_xor_sync(FULL, snd, 4);
            t4[i] = (up ? r[i + 4] : r[i]) + recv;
        }
    }
    float t2[2];
    {
        const bool up = (lane & 8) != 0;
#pragma unroll
        for (int i = 0; i < 2; i++) {
            float snd  = up ? t4[i] : t4[i + 2];
            float recv = __shfl_xor_sync(FULL, snd, 8);
            t2[i] = (up ? t4[i + 2] : t4[i]) + recv;
        }
    }
    float t1;
    {
        const bool up = (lane & 16) != 0;
        float snd  = up ? t2[0] : t2[1];
        float recv = __shfl_xor_sync(FULL, snd, 16);
        t1 = (up ? t2[1] : t2[0]) + recv;
    }
    // diag + lgsum across the 8 groups (group-uniform values: masks 4,8,16)
#pragma unroll
    for (int off = 4; off <= 16; off <<= 1) {
        diag  += __shfl_xor_sync(FULL, diag,  off);
        lgsum += __shfl_xor_sync(FULL, lgsum, off);
    }

    // lane -> sum slot for t1
    const int istar = (((lane >> 2) & 1) << 2) | (((lane >> 3) & 1) << 1) | ((lane >> 4) & 1);
    const int S     = ((istar & 4) ? DD : 0) + (lane & 3) * 4 + (istar & 3);

    __shared__ float smem[NWARP][38];
    smem[wid][S] = t1;
    if (lane == 0) { smem[wid][32] = diag; smem[wid][33] = lgsum; }
    __syncthreads();

    if (tid < 34) {
        float acc = 0.f;
#pragma unroll
        for (int w = 0; w < NWARP; w++) acc += smem[w][tid];
        atomicAdd(&g_acc[layer][tid], acc);      // REDG (result unused)
    }
}

// ---------------------------------------------------------------------------
// Kernel 2: finalize, PDL. Ramps during accum; griddepcontrol.wait releases
// after accum's grid completes + flushes. Computes scalar, re-zeroes state.
// ---------------------------------------------------------------------------
__global__ void finalize_kernel(float* __restrict__ out) {
    asm volatile("griddepcontrol.wait;" ::: "memory");

    const int lane = threadIdx.x;   // one warp
    float a1 = 0.f, a2 = 0.f;
    if (lane < LAYERS) {
        float row[36];
        const float4* rp = reinterpret_cast<const float4*>(&g_acc[lane][0]);
#pragma unroll
        for (int i = 0; i < 9; i++) {            // 9 x LDG.128, MLP=9
            float4 q = __ldcg(&rp[i]);
            row[4*i+0] = q.x; row[4*i+1] = q.y; row[4*i+2] = q.z; row[4*i+3] = q.w;
        }
        const float lgs = row[33];
        float dot = 0.f, spt = 0.f;
#pragma unroll
        for (int d = 0; d < DD; d++) {
            float sp  = row[d];
            float slq = row[DD + d] - lgs;       // sum log_q[d]
            dot += sp * slq;
            spt += sp;
        }
        a1 = dot - row[32];
        const float invt = 1.0f / spt;
        float ls = 0.f;
#pragma unroll
        for (int d = 0; d < DD; d++)
            ls += __logf(row[d] * invt + 1e-8f);
        a2 = -ls / (float)DD;
    }
#pragma unroll
    for (int off = 16; off > 0; off >>= 1) {
        a1 += __shfl_xor_sync(FULL, a1, off);
        a2 += __shfl_xor_sync(FULL, a2, off);
    }
    if (lane == 0) {
        const float aux1 = a1 / (2.0f * (float)LAYERS);
        const float aux2 = a2 / (float)LAYERS;
        out[0] = 0.01f * (aux1 + aux2);          // ALPHA*(BETA*aux1 + aux2)
    }

    __syncwarp();
    float4* gz = reinterpret_cast<float4*>(&g_acc[0][0]);
    const float4 z = make_float4(0.f, 0.f, 0.f, 0.f);
#pragma unroll
    for (int i = lane; i < LAYERS * 36 / 4; i += 32)
        gz[i] = z;
}

extern "C" void kernel_launch(void* const* d_in, const int* in_sizes, int n_in,
                              void* d_out, int out_size) {
    const float* x = (const float*)d_in[0];
    float* out = (float*)d_out;

    accum_kernel<<<NBLK, TPB>>>(x);

    cudaLaunchConfig_t cfg = {};
    cfg.gridDim  = dim3(1, 1, 1);
    cfg.blockDim = dim3(32, 1, 1);
    cfg.dynamicSmemBytes = 0;
    cfg.stream = 0;
    cudaLaunchAttribute attr[1];
    attr[0].id = cudaLaunchAttributeProgrammaticStreamSerialization;
    attr[0].val.programmaticStreamSerializationAllowed = 1;
    cfg.attrs = attr;
    cfg.numAttrs = 1;
    cudaLaunchKernelEx(&cfg, finalize_kernel, out);
}

// round 11
// speedup vs baseline: 1.0036x; 1.0036x over previous
#include <cuda_runtime.h>

#define LAYERS 12
#define NROW   4096
#define DD     16
#define TPB    256
#define QPT    8                                   // quarter-rows per thread
#define NBLK   96                                  // 8 blocks per layer
#define NWARP  (TPB / 32)
#define FULL   0xffffffffu

// Per-layer accumulators, padded to 36 floats (144B, 16B-aligned).
// Slots: [0..15]=sum p, [16..31]=sum log_q (lg already folded in), [32]=sum diag.
// Zeroed at module load; finalize re-zeroes after use (deterministic replays).
__device__ __align__(16) float g_acc[LAYERS][36];

// ---------------------------------------------------------------------------
// Kernel 1: per-layer sums. Champion config (96 blocks x 256, QPT=8), REDG
// atomics, no fences — PDL's implicit completion trigger gives visibility.
// ---------------------------------------------------------------------------
__global__ void __launch_bounds__(TPB) accum_kernel(const float* __restrict__ x) {
    const int tid   = threadIdx.x;
    const int lane  = tid & 31;
    const int wid   = tid >> 5;
    const int layer = blockIdx.x >> 3;              // 8 blocks/layer, uniform

    // 8 quarter-rows from 8 independent rows; 4 consecutive lanes = one row.
    const int qbase = blockIdx.x * (TPB * QPT) + tid;
    float4 a[QPT];
#pragma unroll
    for (int k = 0; k < QPT; k++)
        a[k] = reinterpret_cast<const float4*>(x)[qbase + k * TPB];

    // No max-subtract: inputs are N(0,1); exp() cannot overflow fp32.
    float r[8];                 // [0..3] = sum_k p[d], [4..7] = sum_k log_q[d]
    float diag = 0.f;           // lane-local sum p*log_q
#pragma unroll
    for (int i = 0; i < 4; i++) r[i] = r[i + 4] = 0.f;

#pragma unroll
    for (int k = 0; k < QPT; k++) {
        float v[4] = { a[k].x, a[k].y, a[k].z, a[k].w };
        float e[4];
        float u = 0.f, t = 0.f;
#pragma unroll
        for (int i = 0; i < 4; i++) {
            e[i] = __expf(v[i]);
            u += e[i];
            t = fmaf(e[i], v[i], t);            // lane-local sum e*v
        }
        float s = u;                             // row sum across 4 lanes
        s += __shfl_xor_sync(FULL, s, 1);
        s += __shfl_xor_sync(FULL, s, 2);
        const float inv = 1.0f / s;
        const float lg  = __logf(s);

        diag = fmaf(inv, t - lg * u, diag);      // sum_i p*(v - log s)

#pragma unroll
        for (int i = 0; i < 4; i++) {
            r[i]     = fmaf(e[i], inv, r[i]);    // p accumulation
            r[i + 4] += v[i] - lg;                // log_q accumulated DIRECTLY
        }
    }

    // ---- recursive-halving warp reduce of r: masks {4,8,16} (7 SHFLs) ----
    float t4[4];
    {
        const bool up = (lane & 4) != 0;
#pragma unroll
        for (int i = 0; i < 4; i++) {
            float snd  = up ? r[i] : r[i + 4];
            float recv = __shfl_xor_sync(FULL, snd, 4);
            t4[i] = (up ? r[i + 4] : r[i]) + recv;
        }
    }
    float t2[2];
    {
        const bool up = (lane & 8) != 0;
#pragma unroll
        for (int i = 0; i < 2; i++) {
            float snd  = up ? t4[i] : t4[i + 2];
            float recv = __shfl_xor_sync(FULL, snd, 8);
            t2[i] = (up ? t4[i + 2] : t4[i]) + recv;
        }
    }
    float t1;
    {
        const bool up = (lane & 16) != 0;
        float snd  = up ? t2[0] : t2[1];
        float recv = __shfl_xor_sync(FULL, snd, 16);
        t1 = (up ? t2[1] : t2[0]) + recv;
    }
    // diag butterfly
#pragma unroll
    for (int off = 16; off > 0; off >>= 1)
        diag += __shfl_xor_sync(FULL, diag, off);

    // lane -> sum slot for t1
    const int istar = (((lane >> 2) & 1) << 2) | (((lane >> 3) & 1) << 1) | ((lane >> 4) & 1);
    const int S     = ((istar & 4) ? DD : 0) + (lane & 3) * 4 + (istar & 3);

    __shared__ float smem[NWARP][34];
    smem[wid][S] = t1;
    if (lane == 0) smem[wid][32] = diag;
    __syncthreads();

    if (tid < 33) {
        float acc = 0.f;
#pragma unroll
        for (int w = 0; w < NWARP; w++) acc += smem[w][tid];
        atomicAdd(&g_acc[layer][tid], acc);      // REDG (no return)
    }
}

// ---------------------------------------------------------------------------
// Kernel 2: finalize, PDL. One warp per layer; lanes parallel over d so the
// exposed dependent chain is ~700 cycles instead of ~1500.
// ---------------------------------------------------------------------------
__global__ void __launch_bounds__(384) finalize_kernel(float* __restrict__ out) {
    asm volatile("griddepcontrol.wait;" ::: "memory");

    const int tid  = threadIdx.x;
    const int w    = tid >> 5;       // warp = layer (w < 12)
    const int lane = tid & 31;

    __shared__ float s_a1[LAYERS], s_a2[LAYERS];

    if (w < LAYERS) {
        // Parallel loads: lane d<16 owns dimension d.
        float sp  = (lane < DD) ? __ldcg(&g_acc[w][lane])      : 0.f;
        float slq = (lane < DD) ? __ldcg(&g_acc[w][DD + lane]) : 0.f;
        float diag = __ldcg(&g_acc[w][32]);      // broadcast load (uniform addr)

        float dot = sp * slq;
        float spt = sp;
#pragma unroll
        for (int off = 16; off > 0; off >>= 1) {
            dot += __shfl_xor_sync(FULL, dot, off);
            spt += __shfl_xor_sync(FULL, spt, off);
        }
        // one log per lane
        const float invt = 1.0f / spt;
        float ls = (lane < DD) ? __logf(sp * invt + 1e-8f) : 0.f;
#pragma unroll
        for (int off = 16; off > 0; off >>= 1)
            ls += __shfl_xor_sync(FULL, ls, off);

        if (lane == 0) {
            s_a1[w] = dot - diag;
            s_a2[w] = -ls / (float)DD;
        }
    }
    __syncthreads();

    if (tid < 32) {
        float a1 = (lane < LAYERS) ? s_a1[lane] : 0.f;
        float a2 = (lane < LAYERS) ? s_a2[lane] : 0.f;
#pragma unroll
        for (int off = 16; off > 0; off >>= 1) {
            a1 += __shfl_xor_sync(FULL, a1, off);
            a2 += __shfl_xor_sync(FULL, a2, off);
        }
        if (lane == 0) {
            const float aux1 = a1 / (2.0f * (float)LAYERS);
            const float aux2 = a2 / (float)LAYERS;
            out[0] = 0.01f * (aux1 + aux2);      // ALPHA*(BETA*aux1 + aux2)
        }
    }

    // Re-zero accumulators for the next replay (reads all completed before
    // the __syncthreads above).
    if (tid < LAYERS * 36 / 4) {
        float4* gz = reinterpret_cast<float4*>(&g_acc[0][0]);
        gz[tid] = make_float4(0.f, 0.f, 0.f, 0.f);
    }
}

extern "C" void kernel_launch(void* const* d_in, const int* in_sizes, int n_in,
                              void* d_out, int out_size) {
    const float* x = (const float*)d_in[0];
    float* out = (float*)d_out;

    accum_kernel<<<NBLK, TPB>>>(x);

    cudaLaunchConfig_t cfg = {};
    cfg.gridDim  = dim3(1, 1, 1);
    cfg.blockDim = dim3(384, 1, 1);
    cfg.dynamicSmemBytes = 0;
    cfg.stream = 0;
    cudaLaunchAttribute attr[1];
    attr[0].id = cudaLaunchAttributeProgrammaticStreamSerialization;
    attr[0].val.programmaticStreamSerializationAllowed = 1;
    cfg.attrs = attr;
    cfg.numAttrs = 1;
    cudaLaunchKernelEx(&cfg, finalize_kernel, out);
}